// round 6
// baseline (speedup 1.0000x reference)
#include <cuda_runtime.h>
#include <cuda_bf16.h>

// SceneContraction: means = contract(mean); cov_out = J cov J^T where ||mean||>=1 else cov.
// J = g*I + c*x x^T, g = inv*(2-inv), c = 2*inv^3*(inv-1), inv = 1/||x||.
//
// R6: 1 sample/thread + smem staging. Block of 256 threads = 256 samples
// = 768 float4 total (exactly 3 coalesced float4 per thread for fill/drain).
// Compute reads scalar LDS at strides 3 (mean) and 9 (cov) - both coprime
// with 32 banks -> conflict-free. Low register count -> high occupancy -> MLP.

#define THREADS 256
#define F4_PER_BLOCK (12 * THREADS / 4)   // 768 float4 (mean 192 + cov 576)
#define M4_PER_BLOCK (3 * THREADS / 4)    // 192
#define C4_PER_BLOCK (9 * THREADS / 4)    // 576

__global__ __launch_bounds__(THREADS, 6)
void scene_contract_kernel(const float4* __restrict__ mean4,
                           const float4* __restrict__ cov4,
                           float4* __restrict__ mout4,
                           float4* __restrict__ cout4,
                           int nsamp) {
    __shared__ float4 sbuf[F4_PER_BLOCK];         // 12 KB: [mean 192 f4][cov 576 f4]
    float* sf = (float*)sbuf;

    const int t = threadIdx.x;
    const int mbase = blockIdx.x * M4_PER_BLOCK;  // into mean4
    const int cbase = blockIdx.x * C4_PER_BLOCK;  // into cov4

    // ---- coalesced fill: 3 float4 per thread ----
    {
        // mean: first 192 float4 slots <- threads 0..191 (one pass), pad via loop
        if (t < M4_PER_BLOCK) sbuf[t] = mean4[mbase + t];
        // cov: 576 float4 -> slots 192..767
        sbuf[M4_PER_BLOCK + t]           = cov4[cbase + t];
        sbuf[M4_PER_BLOCK + THREADS + t] = cov4[cbase + THREADS + t];
        if (t < C4_PER_BLOCK - 2 * THREADS)  // remaining 64
            sbuf[M4_PER_BLOCK + 2 * THREADS + t] = cov4[cbase + 2 * THREADS + t];
    }
    __syncthreads();

    // ---- compute: one sample per thread ----
    {
        float* xm = sf + 3 * t;                       // stride-3: conflict-free
        float* C  = sf + 4 * M4_PER_BLOCK + 9 * t;    // stride-9: conflict-free

        float x0 = xm[0], x1 = xm[1], x2 = xm[2];
        float c0 = C[0], c1 = C[1], c2 = C[2],
              c3 = C[3], c4 = C[4], c5 = C[5],
              c6 = C[6], c7 = C[7], c8 = C[8];

        float msq = x0 * x0 + x1 * x1 + x2 * x2;
        bool contract = (msq >= 1.0f);

        float inv = rsqrtf(msq);
        float gg = inv * (2.0f - inv);                     // (2m-1)/m^2
        float cc = 2.0f * inv * inv * inv * (inv - 1.0f);  // 2(1-m)/m^4

        xm[0] = contract ? gg * x0 : x0;
        xm[1] = contract ? gg * x1 : x1;
        xm[2] = contract ? gg * x2 : x2;

        // u = x^T C
        float u0 = x0 * c0 + x1 * c3 + x2 * c6;
        float u1 = x0 * c1 + x1 * c4 + x2 * c7;
        float u2 = x0 * c2 + x1 * c5 + x2 * c8;

        // T = J*C = g*C + c*x u^T
        float T00 = gg * c0 + cc * x0 * u0;
        float T01 = gg * c1 + cc * x0 * u1;
        float T02 = gg * c2 + cc * x0 * u2;
        float T10 = gg * c3 + cc * x1 * u0;
        float T11 = gg * c4 + cc * x1 * u1;
        float T12 = gg * c5 + cc * x1 * u2;
        float T20 = gg * c6 + cc * x2 * u0;
        float T21 = gg * c7 + cc * x2 * u1;
        float T22 = gg * c8 + cc * x2 * u2;

        // v = T x
        float v0 = T00 * x0 + T01 * x1 + T02 * x2;
        float v1 = T10 * x0 + T11 * x1 + T12 * x2;
        float v2 = T20 * x0 + T21 * x1 + T22 * x2;

        // O = g*T + c*v x^T  (J symmetric)
        C[0] = contract ? gg * T00 + cc * v0 * x0 : c0;
        C[1] = contract ? gg * T01 + cc * v0 * x1 : c1;
        C[2] = contract ? gg * T02 + cc * v0 * x2 : c2;
        C[3] = contract ? gg * T10 + cc * v1 * x0 : c3;
        C[4] = contract ? gg * T11 + cc * v1 * x1 : c4;
        C[5] = contract ? gg * T12 + cc * v1 * x2 : c5;
        C[6] = contract ? gg * T20 + cc * v2 * x0 : c6;
        C[7] = contract ? gg * T21 + cc * v2 * x1 : c7;
        C[8] = contract ? gg * T22 + cc * v2 * x2 : c8;
    }
    __syncthreads();

    // ---- coalesced drain: 3 float4 per thread ----
    {
        if (t < M4_PER_BLOCK) mout4[mbase + t] = sbuf[t];
        cout4[cbase + t]           = sbuf[M4_PER_BLOCK + t];
        cout4[cbase + THREADS + t] = sbuf[M4_PER_BLOCK + THREADS + t];
        if (t < C4_PER_BLOCK - 2 * THREADS)
            cout4[cbase + 2 * THREADS + t] = sbuf[M4_PER_BLOCK + 2 * THREADS + t];
    }
}

extern "C" void kernel_launch(void* const* d_in, const int* in_sizes, int n_in,
                              void* d_out, int out_size) {
    const float* mean = (const float*)d_in[0];   // [N,3]
    const float* cov  = (const float*)d_in[1];   // [N,3,3]
    float* out = (float*)d_out;                  // [N*3 means][N*9 cov]

    int N = in_sizes[0] / 3;                     // 4,194,304
    int blocks = N / THREADS;                    // 16384, exact

    float4* mout4 = (float4*)out;
    float4* cout4 = (float4*)(out) + (size_t)(3 * N / 4);

    scene_contract_kernel<<<blocks, THREADS>>>(
        (const float4*)mean, (const float4*)cov, mout4, cout4, N);
}

// round 7
// speedup vs baseline: 1.1281x; 1.1281x over previous
#include <cuda_runtime.h>
#include <cstdint>

// SceneContraction, R7: persistent TMA-pipelined kernel.
// Tiles of 1024 samples: mean tile = 12KB, cov tile = 36KB, both contiguous.
// Double-buffered 48KB stages filled with 1D cp.async.bulk (G->S, mbarrier),
// drained with cp.async.bulk (S->G, bulk_group). Compute in place (R5 body).

#define THREADS 256
#define TILE_SAMPLES 1024
#define MEAN_BYTES (TILE_SAMPLES * 3 * 4)       // 12288
#define COV_BYTES  (TILE_SAMPLES * 9 * 4)       // 36864
#define STAGE_BYTES (MEAN_BYTES + COV_BYTES)    // 49152
#define NSTAGES 2
#define SMEM_BYTES (NSTAGES * STAGE_BYTES + 128)

__device__ __forceinline__ uint32_t smem_u32(const void* p) {
    return (uint32_t)__cvta_generic_to_shared(p);
}

__device__ __forceinline__ void bulk_fill(unsigned char* stage_ptr, uint32_t bar,
                                          const float* mean, const float* cov,
                                          int tile) {
    uint32_t dst = smem_u32(stage_ptr);
    const unsigned char* msrc = (const unsigned char*)mean + (size_t)tile * MEAN_BYTES;
    const unsigned char* csrc = (const unsigned char*)cov  + (size_t)tile * COV_BYTES;
    asm volatile("mbarrier.arrive.expect_tx.shared.b64 _, [%0], %1;"
                 :: "r"(bar), "r"((uint32_t)STAGE_BYTES) : "memory");
    asm volatile("cp.async.bulk.shared::cta.global.mbarrier::complete_tx::bytes [%0], [%1], %2, [%3];"
                 :: "r"(dst), "l"(msrc), "r"((uint32_t)MEAN_BYTES), "r"(bar) : "memory");
    asm volatile("cp.async.bulk.shared::cta.global.mbarrier::complete_tx::bytes [%0], [%1], %2, [%3];"
                 :: "r"(dst + (uint32_t)MEAN_BYTES), "l"(csrc), "r"((uint32_t)COV_BYTES), "r"(bar) : "memory");
}

__device__ __forceinline__ void mbar_wait(uint32_t bar, int parity) {
    asm volatile(
        "{\n\t"
        ".reg .pred P1;\n\t"
        "WL%=:\n\t"
        "mbarrier.try_wait.parity.acquire.cta.shared::cta.b64 P1, [%0], %1, 0x989680;\n\t"
        "@P1 bra.uni WD%=;\n\t"
        "bra.uni WL%=;\n\t"
        "WD%=:\n\t"
        "}"
        :: "r"(bar), "r"(parity) : "memory");
}

extern "C" __global__ void __launch_bounds__(THREADS)
scene_contract_kernel(const float* __restrict__ mean,
                      const float* __restrict__ cov,
                      float* __restrict__ mout,
                      float* __restrict__ cout,
                      int ntiles) {
    extern __shared__ unsigned char smem[];
    uint64_t* mbar = (uint64_t*)(smem + NSTAGES * STAGE_BYTES);
    const int t = threadIdx.x;

    if (t == 0) {
        #pragma unroll
        for (int s = 0; s < NSTAGES; s++)
            asm volatile("mbarrier.init.shared.b64 [%0], %1;"
                         :: "r"(smem_u32(&mbar[s])), "r"(1) : "memory");
    }
    __syncthreads();

    // this block handles tiles blockIdx.x + k*gridDim.x
    int nt = 0;
    if ((int)blockIdx.x < ntiles)
        nt = (ntiles - 1 - (int)blockIdx.x) / gridDim.x + 1;

    if (t == 0) {
        if (nt > 0) bulk_fill(smem, smem_u32(&mbar[0]), mean, cov, blockIdx.x);
        if (nt > 1) bulk_fill(smem + STAGE_BYTES, smem_u32(&mbar[1]), mean, cov,
                              blockIdx.x + gridDim.x);
    }

    int ph0 = 0, ph1 = 0;

    for (int k = 0; k < nt; k++) {
        const int s = k & 1;
        const int tile = blockIdx.x + k * gridDim.x;
        unsigned char* stage = smem + s * STAGE_BYTES;
        uint32_t bar = smem_u32(&mbar[s]);

        mbar_wait(bar, s ? ph1 : ph0);
        if (s) ph1 ^= 1; else ph0 ^= 1;

        // ---- compute: 4 samples/thread, vectorized smem access (R5 body) ----
        {
            float4* smean4 = (float4*)stage;                 // 768 f4
            float4* scov4  = (float4*)(stage + MEAN_BYTES);  // 2304 f4

            float xm[12];
            float cv[36];
            #pragma unroll
            for (int i = 0; i < 3; i++) {
                float4 v = smean4[3 * t + i];
                xm[4*i+0] = v.x; xm[4*i+1] = v.y; xm[4*i+2] = v.z; xm[4*i+3] = v.w;
            }
            #pragma unroll
            for (int i = 0; i < 9; i++) {
                float4 v = scov4[9 * t + i];
                cv[4*i+0] = v.x; cv[4*i+1] = v.y; cv[4*i+2] = v.z; cv[4*i+3] = v.w;
            }

            #pragma unroll
            for (int sIdx = 0; sIdx < 4; sIdx++) {
                float x0 = xm[3*sIdx+0], x1 = xm[3*sIdx+1], x2 = xm[3*sIdx+2];
                float* C = cv + 9 * sIdx;

                float msq = x0*x0 + x1*x1 + x2*x2;
                bool contract = (msq >= 1.0f);

                float inv = rsqrtf(msq);
                float gg = inv * (2.0f - inv);                     // (2m-1)/m^2
                float cc = 2.0f * inv * inv * inv * (inv - 1.0f);  // 2(1-m)/m^4

                xm[3*sIdx+0] = contract ? gg * x0 : x0;
                xm[3*sIdx+1] = contract ? gg * x1 : x1;
                xm[3*sIdx+2] = contract ? gg * x2 : x2;

                float u0 = x0*C[0] + x1*C[3] + x2*C[6];
                float u1 = x0*C[1] + x1*C[4] + x2*C[7];
                float u2 = x0*C[2] + x1*C[5] + x2*C[8];

                float T00 = gg*C[0] + cc*x0*u0;
                float T01 = gg*C[1] + cc*x0*u1;
                float T02 = gg*C[2] + cc*x0*u2;
                float T10 = gg*C[3] + cc*x1*u0;
                float T11 = gg*C[4] + cc*x1*u1;
                float T12 = gg*C[5] + cc*x1*u2;
                float T20 = gg*C[6] + cc*x2*u0;
                float T21 = gg*C[7] + cc*x2*u1;
                float T22 = gg*C[8] + cc*x2*u2;

                float v0 = T00*x0 + T01*x1 + T02*x2;
                float v1 = T10*x0 + T11*x1 + T12*x2;
                float v2 = T20*x0 + T21*x1 + T22*x2;

                C[0] = contract ? gg*T00 + cc*v0*x0 : C[0];
                C[1] = contract ? gg*T01 + cc*v0*x1 : C[1];
                C[2] = contract ? gg*T02 + cc*v0*x2 : C[2];
                C[3] = contract ? gg*T10 + cc*v1*x0 : C[3];
                C[4] = contract ? gg*T11 + cc*v1*x1 : C[4];
                C[5] = contract ? gg*T12 + cc*v1*x2 : C[5];
                C[6] = contract ? gg*T20 + cc*v2*x0 : C[6];
                C[7] = contract ? gg*T21 + cc*v2*x1 : C[7];
                C[8] = contract ? gg*T22 + cc*v2*x2 : C[8];
            }

            #pragma unroll
            for (int i = 0; i < 3; i++)
                smean4[3*t+i] = make_float4(xm[4*i+0], xm[4*i+1], xm[4*i+2], xm[4*i+3]);
            #pragma unroll
            for (int i = 0; i < 9; i++)
                scov4[9*t+i] = make_float4(cv[4*i+0], cv[4*i+1], cv[4*i+2], cv[4*i+3]);
        }

        // make generic-proxy smem writes visible to async proxy, then sync
        asm volatile("fence.proxy.async.shared::cta;" ::: "memory");
        __syncthreads();

        if (t == 0) {
            uint32_t src = smem_u32(stage);
            unsigned char* mdst = (unsigned char*)mout + (size_t)tile * MEAN_BYTES;
            unsigned char* cdst = (unsigned char*)cout + (size_t)tile * COV_BYTES;
            asm volatile("cp.async.bulk.global.shared::cta.bulk_group [%0], [%1], %2;"
                         :: "l"(mdst), "r"(src), "r"((uint32_t)MEAN_BYTES) : "memory");
            asm volatile("cp.async.bulk.global.shared::cta.bulk_group [%0], [%1], %2;"
                         :: "l"(cdst), "r"(src + (uint32_t)MEAN_BYTES), "r"((uint32_t)COV_BYTES) : "memory");
            asm volatile("cp.async.bulk.commit_group;" ::: "memory");
            if (k + 2 < nt) {
                // stage s is read by the store just committed; wait until all
                // committed stores have finished READING smem, then refill.
                asm volatile("cp.async.bulk.wait_group.read 0;" ::: "memory");
                bulk_fill(stage, bar, mean, cov, tile + 2 * gridDim.x);
            }
        }
        // No extra barrier: iteration k+1 works on the other stage, whose fill
        // was ordered after its store's reads completed (wait_group.read 0).
    }

    // ensure final stores fully complete before exit
    if (t == 0)
        asm volatile("cp.async.bulk.wait_group 0;" ::: "memory");
}

extern "C" void kernel_launch(void* const* d_in, const int* in_sizes, int n_in,
                              void* d_out, int out_size) {
    const float* mean = (const float*)d_in[0];   // [N,3]
    const float* cov  = (const float*)d_in[1];   // [N,3,3]
    float* out = (float*)d_out;                  // [N*3 means][N*9 cov]

    int N = in_sizes[0] / 3;                     // 4,194,304
    int ntiles = N / TILE_SAMPLES;               // 4096, exact

    float* mout = out;
    float* cout = out + (size_t)3 * N;

    cudaFuncSetAttribute(scene_contract_kernel,
                         cudaFuncAttributeMaxDynamicSharedMemorySize, SMEM_BYTES);

    int blocks = 2 * 148;                        // 2 CTAs/SM, persistent
    if (blocks > ntiles) blocks = ntiles;
    scene_contract_kernel<<<blocks, THREADS, SMEM_BYTES>>>(
        mean, cov, mout, cout, ntiles);
}

// round 10
// speedup vs baseline: 1.2210x; 1.0824x over previous
#include <cuda_runtime.h>
#include <cuda_bf16.h>

// SceneContraction: means = contract(mean); cov_out = J cov J^T where ||mean||>=1 else cov.
// J = g*I + c*x x^T, g = inv*(2-inv), c = 2*inv^3*(inv-1), inv = 1/||x||.
//
// R8 = R5 (best: smem-staged coalesced I/O, 4 samples/thread, vectorized LDS/STS)
//    + __launch_bounds__(256,4) to force <=64 regs -> 4 CTAs/SM (32 warps)
//    + .cs streaming cache hints on all global loads/stores (pure stream,
//      no reuse -> evict-first keeps L2 clean for the opposite stream).

#define THREADS 256
#define M4_PER_BLOCK (3 * THREADS) // 768 float4 of mean per block
#define C4_PER_BLOCK (9 * THREADS) // 2304 float4 of cov per block

__device__ __forceinline__ float4 ldcs4(const float4* p) {
    float4 v;
    asm volatile("ld.global.cs.v4.f32 {%0,%1,%2,%3}, [%4];"
                 : "=f"(v.x), "=f"(v.y), "=f"(v.z), "=f"(v.w) : "l"(p));
    return v;
}
__device__ __forceinline__ void stcs4(float4* p, float4 v) {
    asm volatile("st.global.cs.v4.f32 [%0], {%1,%2,%3,%4};"
                 :: "l"(p), "f"(v.x), "f"(v.y), "f"(v.z), "f"(v.w) : "memory");
}

__global__ __launch_bounds__(THREADS, 4)
void scene_contract_kernel(const float4* __restrict__ mean4,
                           const float4* __restrict__ cov4,
                           float4* __restrict__ mout4,
                           float4* __restrict__ cout4,
                           int ngroups) {
    __shared__ float4 smean[M4_PER_BLOCK];  // 12 KB
    __shared__ float4 scov[C4_PER_BLOCK];   // 36 KB

    const int t = threadIdx.x;
    const int mbase = blockIdx.x * M4_PER_BLOCK;
    const int cbase = blockIdx.x * C4_PER_BLOCK;

    // ---- coalesced fill (grid is an exact multiple; no bounds checks) ----
#pragma unroll
    for (int k = 0; k < 3; k++)
        smean[k * THREADS + t] = ldcs4(&mean4[mbase + k * THREADS + t]);
#pragma unroll
    for (int k = 0; k < 9; k++)
        scov[k * THREADS + t] = ldcs4(&cov4[cbase + k * THREADS + t]);
    __syncthreads();

    // ---- per-thread compute on private smem region ----
    {
        float xm[12];
        float cv[36];

#pragma unroll
        for (int i = 0; i < 3; i++) {
            float4 v = smean[3 * t + i];
            xm[4 * i + 0] = v.x; xm[4 * i + 1] = v.y;
            xm[4 * i + 2] = v.z; xm[4 * i + 3] = v.w;
        }
#pragma unroll
        for (int i = 0; i < 9; i++) {
            float4 v = scov[9 * t + i];
            cv[4 * i + 0] = v.x; cv[4 * i + 1] = v.y;
            cv[4 * i + 2] = v.z; cv[4 * i + 3] = v.w;
        }

#pragma unroll
        for (int s = 0; s < 4; s++) {
            float x0 = xm[3 * s + 0];
            float x1 = xm[3 * s + 1];
            float x2 = xm[3 * s + 2];
            float* C = cv + 9 * s;

            float msq = x0 * x0 + x1 * x1 + x2 * x2;
            bool contract = (msq >= 1.0f);

            float inv = rsqrtf(msq);
            float gg = inv * (2.0f - inv);                      // (2m-1)/m^2
            float cc = 2.0f * inv * inv * inv * (inv - 1.0f);   // 2(1-m)/m^4

            xm[3 * s + 0] = contract ? gg * x0 : x0;
            xm[3 * s + 1] = contract ? gg * x1 : x1;
            xm[3 * s + 2] = contract ? gg * x2 : x2;

            // u = x^T C
            float u0 = x0 * C[0] + x1 * C[3] + x2 * C[6];
            float u1 = x0 * C[1] + x1 * C[4] + x2 * C[7];
            float u2 = x0 * C[2] + x1 * C[5] + x2 * C[8];

            // T = J*C = g*C + c*x u^T
            float T00 = gg * C[0] + cc * x0 * u0;
            float T01 = gg * C[1] + cc * x0 * u1;
            float T02 = gg * C[2] + cc * x0 * u2;
            float T10 = gg * C[3] + cc * x1 * u0;
            float T11 = gg * C[4] + cc * x1 * u1;
            float T12 = gg * C[5] + cc * x1 * u2;
            float T20 = gg * C[6] + cc * x2 * u0;
            float T21 = gg * C[7] + cc * x2 * u1;
            float T22 = gg * C[8] + cc * x2 * u2;

            // v = T x
            float v0 = T00 * x0 + T01 * x1 + T02 * x2;
            float v1 = T10 * x0 + T11 * x1 + T12 * x2;
            float v2 = T20 * x0 + T21 * x1 + T22 * x2;

            // O = g*T + c*v x^T  (J symmetric)
            C[0] = contract ? gg * T00 + cc * v0 * x0 : C[0];
            C[1] = contract ? gg * T01 + cc * v0 * x1 : C[1];
            C[2] = contract ? gg * T02 + cc * v0 * x2 : C[2];
            C[3] = contract ? gg * T10 + cc * v1 * x0 : C[3];
            C[4] = contract ? gg * T11 + cc * v1 * x1 : C[4];
            C[5] = contract ? gg * T12 + cc * v1 * x2 : C[5];
            C[6] = contract ? gg * T20 + cc * v2 * x0 : C[6];
            C[7] = contract ? gg * T21 + cc * v2 * x1 : C[7];
            C[8] = contract ? gg * T22 + cc * v2 * x2 : C[8];
        }

        // write results back to private smem region (no cross-thread hazard)
#pragma unroll
        for (int i = 0; i < 3; i++)
            smean[3 * t + i] = make_float4(xm[4 * i + 0], xm[4 * i + 1],
                                           xm[4 * i + 2], xm[4 * i + 3]);
#pragma unroll
        for (int i = 0; i < 9; i++)
            scov[9 * t + i] = make_float4(cv[4 * i + 0], cv[4 * i + 1],
                                          cv[4 * i + 2], cv[4 * i + 3]);
    }
    __syncthreads();

    // ---- coalesced drain ----
#pragma unroll
    for (int k = 0; k < 3; k++)
        stcs4(&mout4[mbase + k * THREADS + t], smean[k * THREADS + t]);
#pragma unroll
    for (int k = 0; k < 9; k++)
        stcs4(&cout4[cbase + k * THREADS + t], scov[k * THREADS + t]);
}

extern "C" void kernel_launch(void* const* d_in, const int* in_sizes, int n_in,
                              void* d_out, int out_size) {
    const float* mean = (const float*)d_in[0];   // [N,3]
    const float* cov  = (const float*)d_in[1];   // [N,3,3]
    float* out = (float*)d_out;                  // [N*3 means][N*9 cov]

    int N = in_sizes[0] / 3;
    int ngroups = N / 4;                         // 1,048,576

    float4* mout4 = (float4*)out;
    float4* cout4 = (float4*)(out) + (size_t)3 * ngroups;

    int blocks = ngroups / THREADS;              // 4096, exact
    scene_contract_kernel<<<blocks, THREADS>>>(
        (const float4*)mean, (const float4*)cov, mout4, cout4, ngroups);
}

// round 13
// speedup vs baseline: 1.2684x; 1.0388x over previous
#include <cuda_runtime.h>
#include <cstdint>

// SceneContraction: means = contract(mean); cov_out = J cov J^T where ||mean||>=1 else cov.
// J = g*I + c*x x^T, g = inv*(2-inv), c = 2*inv^3*(inv-1), inv = 1/||x||.
//
// R11 = R5 structure (smem staging, 4 samples/thread, vectorized LDS/STS,
// coalesced global f4) with:
//   * 128-thread blocks -> 24KB smem -> 6 CTAs/SM: same warp count as R5
//     but 6 phase-offset pipelines per SM (smoother DRAM issue)
//   * cp.async.cg fill (no LDG->reg->STS round trip, lower reg pressure)
//   * no .cs hints, no reg cap (both hurt in R8)

#define THREADS 128
#define M4_PER_BLOCK (3 * THREADS) // 384 float4 mean per block
#define C4_PER_BLOCK (9 * THREADS) // 1152 float4 cov per block

__device__ __forceinline__ void cpasync16(void* smem_dst, const void* gmem_src) {
    uint32_t d = (uint32_t)__cvta_generic_to_shared(smem_dst);
    asm volatile("cp.async.cg.shared.global [%0], [%1], 16;"
                 :: "r"(d), "l"(gmem_src) : "memory");
}

__global__ __launch_bounds__(THREADS)
void scene_contract_kernel(const float4* __restrict__ mean4,
                           const float4* __restrict__ cov4,
                           float4* __restrict__ mout4,
                           float4* __restrict__ cout4) {
    __shared__ float4 smean[M4_PER_BLOCK];  // 6 KB
    __shared__ float4 scov[C4_PER_BLOCK];   // 18 KB

    const int t = threadIdx.x;
    const int mbase = blockIdx.x * M4_PER_BLOCK;
    const int cbase = blockIdx.x * C4_PER_BLOCK;

    // ---- coalesced async fill (grid exact; no bounds checks) ----
#pragma unroll
    for (int k = 0; k < 3; k++)
        cpasync16(&smean[k * THREADS + t], &mean4[mbase + k * THREADS + t]);
#pragma unroll
    for (int k = 0; k < 9; k++)
        cpasync16(&scov[k * THREADS + t], &cov4[cbase + k * THREADS + t]);
    asm volatile("cp.async.commit_group;" ::: "memory");
    asm volatile("cp.async.wait_group 0;" ::: "memory");
    __syncthreads();

    // ---- per-thread compute on private smem region ----
    {
        float xm[12];
        float cv[36];

#pragma unroll
        for (int i = 0; i < 3; i++) {
            float4 v = smean[3 * t + i];
            xm[4 * i + 0] = v.x; xm[4 * i + 1] = v.y;
            xm[4 * i + 2] = v.z; xm[4 * i + 3] = v.w;
        }
#pragma unroll
        for (int i = 0; i < 9; i++) {
            float4 v = scov[9 * t + i];
            cv[4 * i + 0] = v.x; cv[4 * i + 1] = v.y;
            cv[4 * i + 2] = v.z; cv[4 * i + 3] = v.w;
        }

#pragma unroll
        for (int s = 0; s < 4; s++) {
            float x0 = xm[3 * s + 0];
            float x1 = xm[3 * s + 1];
            float x2 = xm[3 * s + 2];
            float* C = cv + 9 * s;

            float msq = x0 * x0 + x1 * x1 + x2 * x2;
            bool contract = (msq >= 1.0f);

            float inv = rsqrtf(msq);
            float gg = inv * (2.0f - inv);                      // (2m-1)/m^2
            float cc = 2.0f * inv * inv * inv * (inv - 1.0f);   // 2(1-m)/m^4

            xm[3 * s + 0] = contract ? gg * x0 : x0;
            xm[3 * s + 1] = contract ? gg * x1 : x1;
            xm[3 * s + 2] = contract ? gg * x2 : x2;

            // u = x^T C
            float u0 = x0 * C[0] + x1 * C[3] + x2 * C[6];
            float u1 = x0 * C[1] + x1 * C[4] + x2 * C[7];
            float u2 = x0 * C[2] + x1 * C[5] + x2 * C[8];

            // T = J*C = g*C + c*x u^T
            float T00 = gg * C[0] + cc * x0 * u0;
            float T01 = gg * C[1] + cc * x0 * u1;
            float T02 = gg * C[2] + cc * x0 * u2;
            float T10 = gg * C[3] + cc * x1 * u0;
            float T11 = gg * C[4] + cc * x1 * u1;
            float T12 = gg * C[5] + cc * x1 * u2;
            float T20 = gg * C[6] + cc * x2 * u0;
            float T21 = gg * C[7] + cc * x2 * u1;
            float T22 = gg * C[8] + cc * x2 * u2;

            // v = T x
            float v0 = T00 * x0 + T01 * x1 + T02 * x2;
            float v1 = T10 * x0 + T11 * x1 + T12 * x2;
            float v2 = T20 * x0 + T21 * x1 + T22 * x2;

            // O = g*T + c*v x^T  (J symmetric)
            C[0] = contract ? gg * T00 + cc * v0 * x0 : C[0];
            C[1] = contract ? gg * T01 + cc * v0 * x1 : C[1];
            C[2] = contract ? gg * T02 + cc * v0 * x2 : C[2];
            C[3] = contract ? gg * T10 + cc * v1 * x0 : C[3];
            C[4] = contract ? gg * T11 + cc * v1 * x1 : C[4];
            C[5] = contract ? gg * T12 + cc * v1 * x2 : C[5];
            C[6] = contract ? gg * T20 + cc * v2 * x0 : C[6];
            C[7] = contract ? gg * T21 + cc * v2 * x1 : C[7];
            C[8] = contract ? gg * T22 + cc * v2 * x2 : C[8];
        }

        // write back to private smem region (no cross-thread hazard)
#pragma unroll
        for (int i = 0; i < 3; i++)
            smean[3 * t + i] = make_float4(xm[4 * i + 0], xm[4 * i + 1],
                                           xm[4 * i + 2], xm[4 * i + 3]);
#pragma unroll
        for (int i = 0; i < 9; i++)
            scov[9 * t + i] = make_float4(cv[4 * i + 0], cv[4 * i + 1],
                                          cv[4 * i + 2], cv[4 * i + 3]);
    }
    __syncthreads();

    // ---- coalesced drain ----
#pragma unroll
    for (int k = 0; k < 3; k++)
        mout4[mbase + k * THREADS + t] = smean[k * THREADS + t];
#pragma unroll
    for (int k = 0; k < 9; k++)
        cout4[cbase + k * THREADS + t] = scov[k * THREADS + t];
}

extern "C" void kernel_launch(void* const* d_in, const int* in_sizes, int n_in,
                              void* d_out, int out_size) {
    const float* mean = (const float*)d_in[0];   // [N,3]
    const float* cov  = (const float*)d_in[1];   // [N,3,3]
    float* out = (float*)d_out;                  // [N*3 means][N*9 cov]

    int N = in_sizes[0] / 3;                     // 4,194,304
    int ngroups = N / 4;                         // 1,048,576

    float4* mout4 = (float4*)out;
    float4* cout4 = (float4*)(out) + (size_t)3 * ngroups;

    int blocks = ngroups / THREADS;              // 8192, exact
    scene_contract_kernel<<<blocks, THREADS>>>(
        (const float4*)mean, (const float4*)cov, mout4, cout4);
}